// round 14
// baseline (speedup 1.0000x reference)
#include <cuda_runtime.h>
#include <cuda_bf16.h>
#include <cuda_fp16.h>
#include <stdint.h>
#include <math.h>

#define B 512
#define T 512
#define D 256
#define H 128        // IC_ENC == CI_ENC == 128
#define G 384        // 3*H
#define NDIR 4       // 0=ic_fwd, 1=ic_bwd, 2=ci_fwd, 3=ci_bwd
#define CLIPV 5.0f
#define KP 256       // K' = D (hi-only fp16 GEMM)
#define NTOT (NDIR * G)   // 1536

// ---------------- device scratch (no runtime allocation allowed) ----------------
__device__ float g_xall[(size_t)B * T * NTOT];              // 1.61 GB
__device__ float g_wpk[NDIR * G * H];                       // packed Whh
__device__ float g_hfinal[2 * B * H];
__device__ __half g_abf[(size_t)B * T * KP];                // A fp16 hi, 134 MB
__device__ __half g_bbf[(size_t)NTOT * KP];                 // B fp16 hi
__device__ float g_bias[NTOT];                              // bih + bhh (folded)

// ---------------- helpers ----------------
__device__ __forceinline__ float sigm(float x) {
    return __fdividef(1.0f, 1.0f + __expf(-x));
}
// fast tanh: 1 - 2/(e^{2x}+1); saturates correctly for |x| large
__device__ __forceinline__ float fast_tanh(float x) {
    float e = __expf(2.0f * x);
    return 1.0f - __fdividef(2.0f, e + 1.0f);
}
__device__ __forceinline__ uint32_t smem_u32(const void* p) {
    uint32_t a;
    asm("{ .reg .u64 t; cvta.to.shared.u64 t, %1; cvt.u32.u64 %0, t; }" : "=r"(a) : "l"(p));
    return a;
}
__device__ __forceinline__ void cpasync16(uint32_t dst, const void* src) {
    asm volatile("cp.async.cg.shared.global [%0], [%1], 16;"
                 :: "r"(dst), "l"(__cvta_generic_to_global(src)) : "memory");
}
__device__ __forceinline__ void cpcommit() {
    asm volatile("cp.async.commit_group;" ::: "memory");
}
__device__ __forceinline__ void cpwait0() {
    asm volatile("cp.async.wait_group 0;" ::: "memory");
}
__device__ __forceinline__ void cpwait1() {
    asm volatile("cp.async.wait_group 1;" ::: "memory");
}
__device__ __forceinline__ void ldsm_x4(uint32_t* r, uint32_t addr) {
    asm volatile("ldmatrix.sync.aligned.m8n8.x4.shared.b16 {%0,%1,%2,%3}, [%4];"
                 : "=r"(r[0]), "=r"(r[1]), "=r"(r[2]), "=r"(r[3]) : "r"(addr));
}
__device__ __forceinline__ void mma16816(float* d, const uint32_t* a, const uint32_t* b) {
    asm volatile(
        "mma.sync.aligned.m16n8k16.row.col.f32.f16.f16.f32 "
        "{%0,%1,%2,%3}, {%4,%5,%6,%7}, {%8,%9}, {%0,%1,%2,%3};"
        : "+f"(d[0]), "+f"(d[1]), "+f"(d[2]), "+f"(d[3])
        : "r"(a[0]), "r"(a[1]), "r"(a[2]), "r"(a[3]), "r"(b[0]), "r"(b[1]));
}
// packed fp32x2 FMA: d = a*b + d elementwise on two lanes
__device__ __forceinline__ void ffma2(unsigned long long& d, unsigned long long a,
                                      unsigned long long b) {
    asm("fma.rn.f32x2 %0, %1, %2, %0;" : "+l"(d) : "l"(a), "l"(b));
}
__device__ __forceinline__ float hsum2(unsigned long long v) {
    float2 f = *(float2*)&v;
    return f.x + f.y;
}

// ---------------- kernel 0: repack Whh into k-major packed layout ----------------
__global__ void repack_whh(const float* __restrict__ icWhh,
                           const float* __restrict__ ciWhh) {
    int idx = blockIdx.x * blockDim.x + threadIdx.x;
    if (idx >= NDIR * G * H) return;
    int dir = idx / (G * H);
    int rem = idx % (G * H);
    int g = rem / H;
    int k = rem % H;
    const float* src = (dir < 2) ? (icWhh + (size_t)dir * G * H)
                                 : (ciWhh + (size_t)(dir - 2) * G * H);
    float v = src[(size_t)g * H + k];
    g_wpk[(size_t)dir * G * H + (size_t)(k >> 2) * (G * 4) + g * 4 + (k & 3)] = v;
}

// ---------------- kernel 0b: data -> fp16 (hi only) -----------------------------
__global__ __launch_bounds__(256) void conv_data(const float* __restrict__ data) {
    size_t i4 = (size_t)blockIdx.x * 256 + threadIdx.x;   // float4 index
    float4 v = ((const float4*)data)[i4];
    ushort4 hv;
    hv.x = __half_as_ushort(__float2half_rn(v.x));
    hv.y = __half_as_ushort(__float2half_rn(v.y));
    hv.z = __half_as_ushort(__float2half_rn(v.z));
    hv.w = __half_as_ushort(__float2half_rn(v.w));
    *(ushort4*)&g_abf[i4 * 4] = hv;
}

// ---------------- kernel 0c: weights -> fp16 hi + folded bias --------------------
__global__ __launch_bounds__(256) void conv_w(
    const float* __restrict__ icWih, const float* __restrict__ icBih,
    const float* __restrict__ ciWih, const float* __restrict__ ciBih,
    const float* __restrict__ icBhh, const float* __restrict__ ciBhh) {
    int idx = blockIdx.x * 256 + threadIdx.x;   // n*256 + k
    int n = idx >> 8;
    int k = idx & 255;
    int dir = n / G;
    int g = n - dir * G;
    const float* Wsel = (dir < 2) ? (icWih + (size_t)dir * G * D)
                                  : (ciWih + (size_t)(dir - 2) * G * D);
    const float* Bsel = (dir < 2) ? (icBih + dir * G) : (ciBih + (dir - 2) * G);
    const float* Bhh  = (dir < 2) ? (icBhh + dir * G) : (ciBhh + (dir - 2) * G);
    float x = Wsel[(size_t)g * D + k];
    g_bbf[(size_t)n * KP + k] = __float2half_rn(x);
    if (k == 0) g_bias[n] = Bsel[g] + Bhh[g];   // fold recurrent bias
}

// ---------------- kernel 1: projection GEMM via mma.sync fp16 (HMMA) ------------
// 128x128 tile, BK=64, 3-stage cp.async, 2 CTAs/SM, single sync/chunk. K'=256.
#define BK 64
#define NCH (KP / BK)      // 4
#define LDS_STRIDE 144     // bytes per smem row (64 fp16 + 8 pad)
#define STG_B (128 * LDS_STRIDE)            // 18432 B per stage per matrix
#define SMEM_PROJ (3 * STG_B * 2 + 512)     // 111104 B

__global__ __launch_bounds__(256, 2) void proj_hmma() {
    extern __shared__ char psm[];
    uint32_t sA = smem_u32(psm);
    uint32_t sB = sA + 3 * STG_B;
    float* bias_sm = (float*)(psm + 6 * STG_B);

    int tid = threadIdx.x;
    int wid = tid >> 5;
    int lid = tid & 31;
    int wm = wid >> 1;            // 0..3
    int wn = wid & 1;             // 0..1

    int n0 = blockIdx.x * 128;            // 12 N-tiles (fastest -> A reuse in L2)
    size_t m0 = (size_t)blockIdx.y * 128; // 2048 M-tiles

    if (tid < 128) bias_sm[tid] = g_bias[n0 + tid];

    const __half* Ag = g_abf + m0 * KP;
    const __half* Bg = g_bbf + (size_t)n0 * KP;

    int aRow = wm * 32 + (lid & 15);
    int aCol = (lid >> 4) * 16;
    int bRow4 = wn * 64 + ((lid >> 4) * 8) + (lid & 7);
    int bCol4 = ((lid >> 3) & 1) * 16;

    float acc[2][8][4];
    #pragma unroll
    for (int mi = 0; mi < 2; mi++)
        #pragma unroll
        for (int nj = 0; nj < 8; nj++)
            #pragma unroll
            for (int q = 0; q < 4; q++) acc[mi][nj][q] = 0.0f;

    #define LOAD_CHUNK(stg, c) do {                                            \
        uint32_t dA = sA + (stg) * STG_B;                                      \
        uint32_t dB = sB + (stg) * STG_B;                                      \
        int ko = (c) * BK;                                                     \
        _Pragma("unroll")                                                      \
        for (int l = 0; l < 4; l++) {                                          \
            int idx = tid + 256 * l;                                           \
            int row = idx >> 3;                                                \
            int c16 = idx & 7;                                                 \
            cpasync16(dA + row * LDS_STRIDE + c16 * 16,                        \
                      Ag + (size_t)row * KP + ko + c16 * 8);                   \
            cpasync16(dB + row * LDS_STRIDE + c16 * 16,                        \
                      Bg + (size_t)row * KP + ko + c16 * 8);                   \
        }                                                                      \
        cpcommit();                                                            \
    } while (0)

    LOAD_CHUNK(0, 0);
    LOAD_CHUNK(1, 1);

    for (int i = 0; i < NCH; i++) {
        if (i == NCH - 1) cpwait0(); else cpwait1();
        __syncthreads();

        if (i + 2 < NCH) LOAD_CHUNK((i + 2) % 3, i + 2);

        uint32_t aBase = sA + (i % 3) * STG_B;
        uint32_t bBase = sB + (i % 3) * STG_B;
        #pragma unroll
        for (int ks = 0; ks < 4; ks++) {
            uint32_t afr[2][4];
            #pragma unroll
            for (int mi = 0; mi < 2; mi++)
                ldsm_x4(afr[mi], aBase + (aRow + mi * 16) * LDS_STRIDE + ks * 32 + aCol);
            uint32_t bfr[8][2];
            #pragma unroll
            for (int nj2 = 0; nj2 < 4; nj2++) {
                uint32_t q[4];
                ldsm_x4(q, bBase + (bRow4 + nj2 * 16) * LDS_STRIDE + ks * 32 + bCol4);
                bfr[nj2 * 2][0] = q[0]; bfr[nj2 * 2][1] = q[1];
                bfr[nj2 * 2 + 1][0] = q[2]; bfr[nj2 * 2 + 1][1] = q[3];
            }
            #pragma unroll
            for (int mi = 0; mi < 2; mi++)
                #pragma unroll
                for (int nj = 0; nj < 8; nj++)
                    mma16816(acc[mi][nj], afr[mi], bfr[nj]);
        }
    }

    int qr = lid >> 2;
    int qc = (lid & 3) * 2;
    #pragma unroll
    for (int mi = 0; mi < 2; mi++) {
        #pragma unroll
        for (int nj = 0; nj < 8; nj++) {
            int lc = wn * 64 + nj * 8 + qc;
            size_t row = m0 + wm * 32 + mi * 16 + qr;
            float2 v0, v1;
            v0.x = acc[mi][nj][0] + bias_sm[lc];
            v0.y = acc[mi][nj][1] + bias_sm[lc + 1];
            v1.x = acc[mi][nj][2] + bias_sm[lc];
            v1.y = acc[mi][nj][3] + bias_sm[lc + 1];
            *(float2*)&g_xall[row * NTOT + n0 + lc] = v0;
            *(float2*)&g_xall[(row + 8) * NTOT + n0 + lc] = v1;
        }
    }
}

// ---------------- kernel 2: recurrent scan (fused GEMM1+gates, 2 barriers) -----
// 256 threads; lane = rg(4) x sub(8). Thread owns rows r = rg*4+m (m 0..3)
// and gate columns g = w*16 + l*8 + sub (l 0..1).
// Phase A computes z/r pre-activations for {g, g+128} directly in registers
// (no Cs staging), applies gates, writes rh. Phase B = GEMM2 + h update.
// XOR bank swizzle on hb/rh column index: c ^ (rg(r) << 3).
#define RT 16
#define SMEM_SCAN ((49152 + 2048 + 2048) * 4)   // 212992 B (Cs removed)

__global__ __launch_bounds__(256) void scan_kernel(
    const float* __restrict__ icH0, const float* __restrict__ ciH0,
    float* __restrict__ out) {

    extern __shared__ float sm[];
    float* Wsm = sm;                 // packed [k4][g][4kk], g in [0,384)
    float* hb  = sm + 49152;         // 16 x 128 (swizzled)
    float* rh  = sm + 49152 + 2048;  // 16 x 128 (swizzled)

    int tid = threadIdx.x;
    int w = tid >> 5;
    int lane = tid & 31;
    int rg = lane >> 3;        // 0..3
    int sub = lane & 7;        // 0..7
    int sw = rg << 3;          // swizzle for this thread's rows (r>>2 == rg)

    int dir = blockIdx.x >> 5;
    int tile = blockIdx.x & 31;
    int b0 = tile * RT;

    const float* h0 = (dir < 2) ? (icH0 + dir * H) : (ciH0 + (dir - 2) * H);

    // load W into SMEM (192 KB), h0 into hb (swizzled)
    {
        const float4* wg = (const float4*)(g_wpk + (size_t)dir * G * H);
        float4* Wsm4 = (float4*)Wsm;
        #pragma unroll
        for (int i = 0; i < (G * H / 4) / 256; i++)
            Wsm4[tid + 256 * i] = wg[tid + 256 * i];
        for (int i = tid; i < RT * H; i += 256) {
            int r = i >> 7, g = i & 127;
            hb[r * 128 + (g ^ (((r >> 2) & 3) << 3))] = h0[g];
        }
    }
    __syncthreads();

    const bool backward = (dir & 1);
    const bool is_ci = (dir >= 2);
    const float* xbase = g_xall + (size_t)b0 * T * NTOT + dir * G;
    const size_t rowstride = (size_t)T * NTOT;

    for (int step = 0; step < T; step++) {
        int t = backward ? (T - 1 - step) : step;
        const float* xt = xbase + (size_t)t * NTOT;

        // prefetch x for gate/update ownership (hidden under GEMM1)
        float xz[4][2], xr[4][2], xn[4][2];
        #pragma unroll
        for (int m = 0; m < 4; m++) {
            const float* xrow = xt + (size_t)(rg * 4 + m) * rowstride;
            #pragma unroll
            for (int l = 0; l < 2; l++) {
                int g = w * 16 + l * 8 + sub;
                xz[m][l] = __ldg(xrow + g);
                xr[m][l] = __ldg(xrow + g + 128);
                xn[m][l] = __ldg(xrow + g + 256);
            }
        }

        // ---- Phase A: fused GEMM1 + gates (accumulators stay in registers) ----
        float z[4][2], hbr[4][2];
        {
            unsigned long long za[4][2], ra[4][2];
            #pragma unroll
            for (int m = 0; m < 4; m++)
                #pragma unroll
                for (int l = 0; l < 2; l++) { za[m][l] = 0ull; ra[m][l] = 0ull; }
            #pragma unroll 2
            for (int k4 = 0; k4 < H / 4; k4++) {
                ulonglong2 wz[2], wr[2], hv[4];
                #pragma unroll
                for (int l = 0; l < 2; l++) {
                    int j = w * 16 + l * 8 + sub;
                    wz[l] = *(const ulonglong2*)&Wsm[(size_t)(k4 * G + j) * 4];
                    wr[l] = *(const ulonglong2*)&Wsm[(size_t)(k4 * G + j + 128) * 4];
                }
                #pragma unroll
                for (int m = 0; m < 4; m++)
                    hv[m] = *(const ulonglong2*)&hb[(rg * 4 + m) * 128 + ((k4 * 4) ^ sw)];
                #pragma unroll
                for (int m = 0; m < 4; m++)
                    #pragma unroll
                    for (int l = 0; l < 2; l++) {
                        ffma2(za[m][l], hv[m].x, wz[l].x);
                        ffma2(za[m][l], hv[m].y, wz[l].y);
                        ffma2(ra[m][l], hv[m].x, wr[l].x);
                        ffma2(ra[m][l], hv[m].y, wr[l].y);
                    }
            }
            #pragma unroll
            for (int m = 0; m < 4; m++)
                #pragma unroll
                for (int l = 0; l < 2; l++) {
                    int r = rg * 4 + m;
                    int g = w * 16 + l * 8 + sub;
                    z[m][l] = sigm(xz[m][l] + hsum2(za[m][l]));
                    float rgt = sigm(xr[m][l] + hsum2(ra[m][l]));
                    float hv = hb[r * 128 + (g ^ sw)];
                    hbr[m][l] = hv;
                    rh[r * 128 + (g ^ sw)] = rgt * hv;
                }
        }
        __syncthreads();

        // ---- Phase B: GEMM2 (n pre-activation) + h update ----
        {
            unsigned long long acc[4][2];
            #pragma unroll
            for (int m = 0; m < 4; m++)
                #pragma unroll
                for (int l = 0; l < 2; l++) acc[m][l] = 0ull;
            #pragma unroll 2
            for (int k4 = 0; k4 < H / 4; k4++) {
                ulonglong2 wv[2], hv[4];
                #pragma unroll
                for (int l = 0; l < 2; l++)
                    wv[l] = *(const ulonglong2*)&Wsm[(size_t)(k4 * G + 256 + w * 16 + l * 8 + sub) * 4];
                #pragma unroll
                for (int m = 0; m < 4; m++)
                    hv[m] = *(const ulonglong2*)&rh[(rg * 4 + m) * 128 + ((k4 * 4) ^ sw)];
                #pragma unroll
                for (int m = 0; m < 4; m++)
                    #pragma unroll
                    for (int l = 0; l < 2; l++) {
                        ffma2(acc[m][l], hv[m].x, wv[l].x);
                        ffma2(acc[m][l], hv[m].y, wv[l].y);
                    }
            }
            int slot = is_ci ? (dir == 2 ? t + 1 : t - 1) : 0;
            #pragma unroll
            for (int m = 0; m < 4; m++)
                #pragma unroll
                for (int l = 0; l < 2; l++) {
                    int r = rg * 4 + m;
                    int g = w * 16 + l * 8 + sub;
                    float nv = fast_tanh(xn[m][l] + hsum2(acc[m][l]));
                    float hn = z[m][l] * hbr[m][l] + (1.0f - z[m][l]) * nv;
                    hn = fminf(CLIPV, fmaxf(-CLIPV, hn));
                    hb[r * 128 + (g ^ sw)] = hn;
                    if (is_ci && slot >= 0 && slot < T) {
                        size_t o = 65536 + (((size_t)(dir - 2) * B + (b0 + r)) * T + slot) * H + g;
                        out[o] = hn;
                    }
                }
        }
        __syncthreads();
    }

    if (dir < 2) {
        for (int i = tid; i < RT * H; i += 256) {
            int r = i >> 7, g = i & 127;
            g_hfinal[((size_t)dir * B + b0 + r) * H + g] =
                hb[r * 128 + (g ^ (((r >> 2) & 3) << 3))];
        }
    }
}

// ---------------- kernel 3: zero the lag-pad slots of ci ----------------
__global__ void zero_pads(float* __restrict__ out) {
    int b = blockIdx.x;
    int g = threadIdx.x;
    out[65536 + ((size_t)b * T + 0) * H + g] = 0.0f;
    out[65536 + (((size_t)B + b) * T + (T - 1)) * H + g] = 0.0f;
}

// ---------------- kernel 4: final linear -> ic_mean, ic_std ----------------
__global__ void final_linear(const float* __restrict__ Wl,
                             const float* __restrict__ bl,
                             float* __restrict__ out) {
    __shared__ float hsm[2 * H];
    int b = blockIdx.x;
    int j = threadIdx.x;
    hsm[j] = g_hfinal[(size_t)b * H + j];
    hsm[H + j] = g_hfinal[((size_t)B + b) * H + j];
    __syncthreads();

    float acc = bl[j];
    const float4* w = (const float4*)&Wl[(size_t)j * (2 * H)];
    #pragma unroll 8
    for (int k4 = 0; k4 < (2 * H) / 4; k4++) {
        float4 wv = w[k4];
        float4 hv = *(const float4*)&hsm[k4 * 4];
        acc += wv.x * hv.x + wv.y * hv.y + wv.z * hv.z + wv.w * hv.w;
    }
    if (j < 64) out[(size_t)b * 64 + j] = acc;
    else out[32768 + (size_t)b * 64 + (j - 64)] = expf(acc);
}

// ---------------- launch ----------------
extern "C" void kernel_launch(void* const* d_in, const int* in_sizes, int n_in,
                              void* d_out, int out_size) {
    const float* data   = (const float*)d_in[0];
    const float* ic_h0  = (const float*)d_in[1];
    const float* ci_h0  = (const float*)d_in[2];
    const float* ic_Wih = (const float*)d_in[3];
    const float* ic_bih = (const float*)d_in[4];
    const float* ic_Whh = (const float*)d_in[5];
    const float* ic_bhh = (const float*)d_in[6];
    const float* ci_Wih = (const float*)d_in[7];
    const float* ci_bih = (const float*)d_in[8];
    const float* ci_Whh = (const float*)d_in[9];
    const float* ci_bhh = (const float*)d_in[10];
    const float* Wl     = (const float*)d_in[11];
    const float* bl     = (const float*)d_in[12];
    float* out = (float*)d_out;

    cudaFuncSetAttribute(scan_kernel, cudaFuncAttributeMaxDynamicSharedMemorySize, SMEM_SCAN);
    cudaFuncSetAttribute(proj_hmma, cudaFuncAttributeMaxDynamicSharedMemorySize, SMEM_PROJ);

    repack_whh<<<(NDIR * G * H + 255) / 256, 256>>>(ic_Whh, ci_Whh);
    conv_data<<<(int)((size_t)B * T * D / 4 / 256), 256>>>(data);
    conv_w<<<NTOT, 256>>>(ic_Wih, ic_bih, ci_Wih, ci_bih, ic_bhh, ci_bhh);

    dim3 pgrid(NTOT / 128, B * T / 128);   // 12 x 2048
    proj_hmma<<<pgrid, 256, SMEM_PROJ>>>();

    scan_kernel<<<NDIR * (B / RT), 256, SMEM_SCAN>>>(ic_h0, ci_h0, out);

    zero_pads<<<B, H>>>(out);
    final_linear<<<B, H>>>(Wl, bl, out);
}

// round 15
// speedup vs baseline: 1.0207x; 1.0207x over previous
#include <cuda_runtime.h>
#include <cuda_bf16.h>
#include <cuda_fp16.h>
#include <stdint.h>
#include <math.h>

#define B 512
#define T 512
#define D 256
#define H 128        // IC_ENC == CI_ENC == 128
#define G 384        // 3*H
#define NDIR 4       // 0=ic_fwd, 1=ic_bwd, 2=ci_fwd, 3=ci_bwd
#define CLIPV 5.0f
#define KP 256       // K' = D (hi-only fp16 GEMM)
#define NTOT (NDIR * G)   // 1536

// ---------------- device scratch (no runtime allocation allowed) ----------------
__device__ float g_xall[(size_t)B * T * NTOT];              // 1.61 GB
__device__ float g_wpk[NDIR * G * H];                       // packed Whh
__device__ float g_hfinal[2 * B * H];
__device__ __half g_abf[(size_t)B * T * KP];                // A fp16 hi, 134 MB
__device__ __half g_bbf[(size_t)NTOT * KP];                 // B fp16 hi
__device__ float g_bias[NTOT];                              // bih + bhh (folded)

// ---------------- helpers ----------------
__device__ __forceinline__ float sigm(float x) {
    return __fdividef(1.0f, 1.0f + __expf(-x));
}
// fast tanh: 1 - 2/(e^{2x}+1); saturates correctly for |x| large
__device__ __forceinline__ float fast_tanh(float x) {
    float e = __expf(2.0f * x);
    return 1.0f - __fdividef(2.0f, e + 1.0f);
}
__device__ __forceinline__ uint32_t smem_u32(const void* p) {
    uint32_t a;
    asm("{ .reg .u64 t; cvta.to.shared.u64 t, %1; cvt.u32.u64 %0, t; }" : "=r"(a) : "l"(p));
    return a;
}
__device__ __forceinline__ void cpasync16(uint32_t dst, const void* src) {
    asm volatile("cp.async.cg.shared.global [%0], [%1], 16;"
                 :: "r"(dst), "l"(__cvta_generic_to_global(src)) : "memory");
}
__device__ __forceinline__ void cpcommit() {
    asm volatile("cp.async.commit_group;" ::: "memory");
}
__device__ __forceinline__ void cpwait0() {
    asm volatile("cp.async.wait_group 0;" ::: "memory");
}
__device__ __forceinline__ void cpwait1() {
    asm volatile("cp.async.wait_group 1;" ::: "memory");
}
__device__ __forceinline__ void ldsm_x4(uint32_t* r, uint32_t addr) {
    asm volatile("ldmatrix.sync.aligned.m8n8.x4.shared.b16 {%0,%1,%2,%3}, [%4];"
                 : "=r"(r[0]), "=r"(r[1]), "=r"(r[2]), "=r"(r[3]) : "r"(addr));
}
__device__ __forceinline__ void mma16816(float* d, const uint32_t* a, const uint32_t* b) {
    asm volatile(
        "mma.sync.aligned.m16n8k16.row.col.f32.f16.f16.f32 "
        "{%0,%1,%2,%3}, {%4,%5,%6,%7}, {%8,%9}, {%0,%1,%2,%3};"
        : "+f"(d[0]), "+f"(d[1]), "+f"(d[2]), "+f"(d[3])
        : "r"(a[0]), "r"(a[1]), "r"(a[2]), "r"(a[3]), "r"(b[0]), "r"(b[1]));
}
// packed fp32x2 FMA: d = a*b + d elementwise on two lanes
__device__ __forceinline__ void ffma2(unsigned long long& d, unsigned long long a,
                                      unsigned long long b) {
    asm("fma.rn.f32x2 %0, %1, %2, %0;" : "+l"(d) : "l"(a), "l"(b));
}
__device__ __forceinline__ float hsum2(unsigned long long v) {
    float2 f = *(float2*)&v;
    return f.x + f.y;
}

// ---------------- kernel 0: repack Whh into k-major packed layout ----------------
__global__ void repack_whh(const float* __restrict__ icWhh,
                           const float* __restrict__ ciWhh) {
    int idx = blockIdx.x * blockDim.x + threadIdx.x;
    if (idx >= NDIR * G * H) return;
    int dir = idx / (G * H);
    int rem = idx % (G * H);
    int g = rem / H;
    int k = rem % H;
    const float* src = (dir < 2) ? (icWhh + (size_t)dir * G * H)
                                 : (ciWhh + (size_t)(dir - 2) * G * H);
    float v = src[(size_t)g * H + k];
    g_wpk[(size_t)dir * G * H + (size_t)(k >> 2) * (G * 4) + g * 4 + (k & 3)] = v;
}

// ---------------- kernel 0b: data -> fp16 (hi only) -----------------------------
__global__ __launch_bounds__(256) void conv_data(const float* __restrict__ data) {
    size_t i4 = (size_t)blockIdx.x * 256 + threadIdx.x;   // float4 index
    float4 v = ((const float4*)data)[i4];
    ushort4 hv;
    hv.x = __half_as_ushort(__float2half_rn(v.x));
    hv.y = __half_as_ushort(__float2half_rn(v.y));
    hv.z = __half_as_ushort(__float2half_rn(v.z));
    hv.w = __half_as_ushort(__float2half_rn(v.w));
    *(ushort4*)&g_abf[i4 * 4] = hv;
}

// ---------------- kernel 0c: weights -> fp16 hi + folded bias --------------------
__global__ __launch_bounds__(256) void conv_w(
    const float* __restrict__ icWih, const float* __restrict__ icBih,
    const float* __restrict__ ciWih, const float* __restrict__ ciBih,
    const float* __restrict__ icBhh, const float* __restrict__ ciBhh) {
    int idx = blockIdx.x * 256 + threadIdx.x;   // n*256 + k
    int n = idx >> 8;
    int k = idx & 255;
    int dir = n / G;
    int g = n - dir * G;
    const float* Wsel = (dir < 2) ? (icWih + (size_t)dir * G * D)
                                  : (ciWih + (size_t)(dir - 2) * G * D);
    const float* Bsel = (dir < 2) ? (icBih + dir * G) : (ciBih + (dir - 2) * G);
    const float* Bhh  = (dir < 2) ? (icBhh + dir * G) : (ciBhh + (dir - 2) * G);
    float x = Wsel[(size_t)g * D + k];
    g_bbf[(size_t)n * KP + k] = __float2half_rn(x);
    if (k == 0) g_bias[n] = Bsel[g] + Bhh[g];   // fold recurrent bias
}

// ---------------- kernel 1: projection GEMM via mma.sync fp16 (HMMA) ------------
// 128x128 tile, BK=64, 3-stage cp.async, 2 CTAs/SM, single sync/chunk. K'=256.
#define BK 64
#define NCH (KP / BK)      // 4
#define LDS_STRIDE 144     // bytes per smem row (64 fp16 + 8 pad)
#define STG_B (128 * LDS_STRIDE)            // 18432 B per stage per matrix
#define SMEM_PROJ (3 * STG_B * 2 + 512)     // 111104 B

__global__ __launch_bounds__(256, 2) void proj_hmma() {
    extern __shared__ char psm[];
    uint32_t sA = smem_u32(psm);
    uint32_t sB = sA + 3 * STG_B;
    float* bias_sm = (float*)(psm + 6 * STG_B);

    int tid = threadIdx.x;
    int wid = tid >> 5;
    int lid = tid & 31;
    int wm = wid >> 1;            // 0..3
    int wn = wid & 1;             // 0..1

    int n0 = blockIdx.x * 128;            // 12 N-tiles (fastest -> A reuse in L2)
    size_t m0 = (size_t)blockIdx.y * 128; // 2048 M-tiles

    if (tid < 128) bias_sm[tid] = g_bias[n0 + tid];

    const __half* Ag = g_abf + m0 * KP;
    const __half* Bg = g_bbf + (size_t)n0 * KP;

    int aRow = wm * 32 + (lid & 15);
    int aCol = (lid >> 4) * 16;
    int bRow4 = wn * 64 + ((lid >> 4) * 8) + (lid & 7);
    int bCol4 = ((lid >> 3) & 1) * 16;

    float acc[2][8][4];
    #pragma unroll
    for (int mi = 0; mi < 2; mi++)
        #pragma unroll
        for (int nj = 0; nj < 8; nj++)
            #pragma unroll
            for (int q = 0; q < 4; q++) acc[mi][nj][q] = 0.0f;

    #define LOAD_CHUNK(stg, c) do {                                            \
        uint32_t dA = sA + (stg) * STG_B;                                      \
        uint32_t dB = sB + (stg) * STG_B;                                      \
        int ko = (c) * BK;                                                     \
        _Pragma("unroll")                                                      \
        for (int l = 0; l < 4; l++) {                                          \
            int idx = tid + 256 * l;                                           \
            int row = idx >> 3;                                                \
            int c16 = idx & 7;                                                 \
            cpasync16(dA + row * LDS_STRIDE + c16 * 16,                        \
                      Ag + (size_t)row * KP + ko + c16 * 8);                   \
            cpasync16(dB + row * LDS_STRIDE + c16 * 16,                        \
                      Bg + (size_t)row * KP + ko + c16 * 8);                   \
        }                                                                      \
        cpcommit();                                                            \
    } while (0)

    LOAD_CHUNK(0, 0);
    LOAD_CHUNK(1, 1);

    for (int i = 0; i < NCH; i++) {
        if (i == NCH - 1) cpwait0(); else cpwait1();
        __syncthreads();

        if (i + 2 < NCH) LOAD_CHUNK((i + 2) % 3, i + 2);

        uint32_t aBase = sA + (i % 3) * STG_B;
        uint32_t bBase = sB + (i % 3) * STG_B;
        #pragma unroll
        for (int ks = 0; ks < 4; ks++) {
            uint32_t afr[2][4];
            #pragma unroll
            for (int mi = 0; mi < 2; mi++)
                ldsm_x4(afr[mi], aBase + (aRow + mi * 16) * LDS_STRIDE + ks * 32 + aCol);
            uint32_t bfr[8][2];
            #pragma unroll
            for (int nj2 = 0; nj2 < 4; nj2++) {
                uint32_t q[4];
                ldsm_x4(q, bBase + (bRow4 + nj2 * 16) * LDS_STRIDE + ks * 32 + bCol4);
                bfr[nj2 * 2][0] = q[0]; bfr[nj2 * 2][1] = q[1];
                bfr[nj2 * 2 + 1][0] = q[2]; bfr[nj2 * 2 + 1][1] = q[3];
            }
            #pragma unroll
            for (int mi = 0; mi < 2; mi++)
                #pragma unroll
                for (int nj = 0; nj < 8; nj++)
                    mma16816(acc[mi][nj], afr[mi], bfr[nj]);
        }
    }

    int qr = lid >> 2;
    int qc = (lid & 3) * 2;
    #pragma unroll
    for (int mi = 0; mi < 2; mi++) {
        #pragma unroll
        for (int nj = 0; nj < 8; nj++) {
            int lc = wn * 64 + nj * 8 + qc;
            size_t row = m0 + wm * 32 + mi * 16 + qr;
            float2 v0, v1;
            v0.x = acc[mi][nj][0] + bias_sm[lc];
            v0.y = acc[mi][nj][1] + bias_sm[lc + 1];
            v1.x = acc[mi][nj][2] + bias_sm[lc];
            v1.y = acc[mi][nj][3] + bias_sm[lc + 1];
            *(float2*)&g_xall[row * NTOT + n0 + lc] = v0;
            *(float2*)&g_xall[(row + 8) * NTOT + n0 + lc] = v1;
        }
    }
}

// ---------------- kernel 2: recurrent scan (fused, software-pipelined) ---------
// 256 threads; lane = rg(4) x sub(8). Thread owns rows r = rg*4+m (m 0..3)
// and gate columns g = w*16 + l*8 + sub (l 0..1).
// Inner k4 loops are register double-buffered: iteration k4 issues k4+1's
// W/h LDS first, then computes k4's FFMA2s -> LDS latency fully covered.
// XOR bank swizzle on hb/rh column index: c ^ (rg(r) << 3).
#define RT 16
#define SMEM_SCAN ((49152 + 2048 + 2048) * 4)   // 212992 B

__global__ __launch_bounds__(256) void scan_kernel(
    const float* __restrict__ icH0, const float* __restrict__ ciH0,
    float* __restrict__ out) {

    extern __shared__ float sm[];
    float* Wsm = sm;                 // packed [k4][g][4kk], g in [0,384)
    float* hb  = sm + 49152;         // 16 x 128 (swizzled)
    float* rh  = sm + 49152 + 2048;  // 16 x 128 (swizzled)

    int tid = threadIdx.x;
    int w = tid >> 5;
    int lane = tid & 31;
    int rg = lane >> 3;        // 0..3
    int sub = lane & 7;        // 0..7
    int sw = rg << 3;          // swizzle for this thread's rows (r>>2 == rg)

    int dir = blockIdx.x >> 5;
    int tile = blockIdx.x & 31;
    int b0 = tile * RT;

    const float* h0 = (dir < 2) ? (icH0 + dir * H) : (ciH0 + (dir - 2) * H);

    // load W into SMEM (192 KB), h0 into hb (swizzled)
    {
        const float4* wg = (const float4*)(g_wpk + (size_t)dir * G * H);
        float4* Wsm4 = (float4*)Wsm;
        #pragma unroll
        for (int i = 0; i < (G * H / 4) / 256; i++)
            Wsm4[tid + 256 * i] = wg[tid + 256 * i];
        for (int i = tid; i < RT * H; i += 256) {
            int r = i >> 7, g = i & 127;
            hb[r * 128 + (g ^ (((r >> 2) & 3) << 3))] = h0[g];
        }
    }
    __syncthreads();

    const bool backward = (dir & 1);
    const bool is_ci = (dir >= 2);
    const float* xbase = g_xall + (size_t)b0 * T * NTOT + dir * G;
    const size_t rowstride = (size_t)T * NTOT;

    int j0 = w * 16 + sub;         // gate col l=0
    int j1 = w * 16 + 8 + sub;     // gate col l=1

    for (int step = 0; step < T; step++) {
        int t = backward ? (T - 1 - step) : step;
        const float* xt = xbase + (size_t)t * NTOT;

        // prefetch x for gate/update ownership (hidden under GEMM1)
        float xz[4][2], xr[4][2], xn[4][2];
        #pragma unroll
        for (int m = 0; m < 4; m++) {
            const float* xrow = xt + (size_t)(rg * 4 + m) * rowstride;
            #pragma unroll
            for (int l = 0; l < 2; l++) {
                int g = w * 16 + l * 8 + sub;
                xz[m][l] = __ldg(xrow + g);
                xr[m][l] = __ldg(xrow + g + 128);
                xn[m][l] = __ldg(xrow + g + 256);
            }
        }

        // ---- Phase A: fused GEMM1 + gates, register double-buffered ----
        float z[4][2], hbr[4][2];
        {
            unsigned long long za[4][2], ra[4][2];
            #pragma unroll
            for (int m = 0; m < 4; m++)
                #pragma unroll
                for (int l = 0; l < 2; l++) { za[m][l] = 0ull; ra[m][l] = 0ull; }

            ulonglong2 wz[2][2], wr[2][2], hv[2][4];
            // prologue: k4 = 0 into buffer 0
            wz[0][0] = *(const ulonglong2*)&Wsm[(size_t)j0 * 4];
            wz[0][1] = *(const ulonglong2*)&Wsm[(size_t)j1 * 4];
            wr[0][0] = *(const ulonglong2*)&Wsm[(size_t)(j0 + 128) * 4];
            wr[0][1] = *(const ulonglong2*)&Wsm[(size_t)(j1 + 128) * 4];
            #pragma unroll
            for (int m = 0; m < 4; m++)
                hv[0][m] = *(const ulonglong2*)&hb[(rg * 4 + m) * 128 + (0 ^ sw)];

            #pragma unroll
            for (int k4 = 0; k4 < H / 4; k4++) {
                int cur = k4 & 1;
                int nxt = cur ^ 1;
                if (k4 + 1 < H / 4) {
                    int kn = k4 + 1;
                    wz[nxt][0] = *(const ulonglong2*)&Wsm[(size_t)(kn * G + j0) * 4];
                    wz[nxt][1] = *(const ulonglong2*)&Wsm[(size_t)(kn * G + j1) * 4];
                    wr[nxt][0] = *(const ulonglong2*)&Wsm[(size_t)(kn * G + j0 + 128) * 4];
                    wr[nxt][1] = *(const ulonglong2*)&Wsm[(size_t)(kn * G + j1 + 128) * 4];
                    #pragma unroll
                    for (int m = 0; m < 4; m++)
                        hv[nxt][m] = *(const ulonglong2*)&hb[(rg * 4 + m) * 128 + ((kn * 4) ^ sw)];
                }
                #pragma unroll
                for (int m = 0; m < 4; m++)
                    #pragma unroll
                    for (int l = 0; l < 2; l++) {
                        ffma2(za[m][l], hv[cur][m].x, wz[cur][l].x);
                        ffma2(za[m][l], hv[cur][m].y, wz[cur][l].y);
                        ffma2(ra[m][l], hv[cur][m].x, wr[cur][l].x);
                        ffma2(ra[m][l], hv[cur][m].y, wr[cur][l].y);
                    }
            }
            #pragma unroll
            for (int m = 0; m < 4; m++)
                #pragma unroll
                for (int l = 0; l < 2; l++) {
                    int r = rg * 4 + m;
                    int g = w * 16 + l * 8 + sub;
                    z[m][l] = sigm(xz[m][l] + hsum2(za[m][l]));
                    float rgt = sigm(xr[m][l] + hsum2(ra[m][l]));
                    float hvv = hb[r * 128 + (g ^ sw)];
                    hbr[m][l] = hvv;
                    rh[r * 128 + (g ^ sw)] = rgt * hvv;
                }
        }
        __syncthreads();

        // ---- Phase B: GEMM2 (n pre-activation), register double-buffered ----
        {
            unsigned long long acc[4][2];
            #pragma unroll
            for (int m = 0; m < 4; m++)
                #pragma unroll
                for (int l = 0; l < 2; l++) acc[m][l] = 0ull;

            ulonglong2 wv[2][2], hv[2][4];
            wv[0][0] = *(const ulonglong2*)&Wsm[(size_t)(256 + j0) * 4];
            wv[0][1] = *(const ulonglong2*)&Wsm[(size_t)(256 + j1) * 4];
            #pragma unroll
            for (int m = 0; m < 4; m++)
                hv[0][m] = *(const ulonglong2*)&rh[(rg * 4 + m) * 128 + (0 ^ sw)];

            #pragma unroll
            for (int k4 = 0; k4 < H / 4; k4++) {
                int cur = k4 & 1;
                int nxt = cur ^ 1;
                if (k4 + 1 < H / 4) {
                    int kn = k4 + 1;
                    wv[nxt][0] = *(const ulonglong2*)&Wsm[(size_t)(kn * G + 256 + j0) * 4];
                    wv[nxt][1] = *(const ulonglong2*)&Wsm[(size_t)(kn * G + 256 + j1) * 4];
                    #pragma unroll
                    for (int m = 0; m < 4; m++)
                        hv[nxt][m] = *(const ulonglong2*)&rh[(rg * 4 + m) * 128 + ((kn * 4) ^ sw)];
                }
                #pragma unroll
                for (int m = 0; m < 4; m++)
                    #pragma unroll
                    for (int l = 0; l < 2; l++) {
                        ffma2(acc[m][l], hv[cur][m].x, wv[cur][l].x);
                        ffma2(acc[m][l], hv[cur][m].y, wv[cur][l].y);
                    }
            }
            int slot = is_ci ? (dir == 2 ? t + 1 : t - 1) : 0;
            #pragma unroll
            for (int m = 0; m < 4; m++)
                #pragma unroll
                for (int l = 0; l < 2; l++) {
                    int r = rg * 4 + m;
                    int g = w * 16 + l * 8 + sub;
                    float nv = fast_tanh(xn[m][l] + hsum2(acc[m][l]));
                    float hn = z[m][l] * hbr[m][l] + (1.0f - z[m][l]) * nv;
                    hn = fminf(CLIPV, fmaxf(-CLIPV, hn));
                    hb[r * 128 + (g ^ sw)] = hn;
                    if (is_ci && slot >= 0 && slot < T) {
                        size_t o = 65536 + (((size_t)(dir - 2) * B + (b0 + r)) * T + slot) * H + g;
                        out[o] = hn;
                    }
                }
        }
        __syncthreads();
    }

    if (dir < 2) {
        for (int i = tid; i < RT * H; i += 256) {
            int r = i >> 7, g = i & 127;
            g_hfinal[((size_t)dir * B + b0 + r) * H + g] =
                hb[r * 128 + (g ^ (((r >> 2) & 3) << 3))];
        }
    }
}

// ---------------- kernel 3: zero the lag-pad slots of ci ----------------
__global__ void zero_pads(float* __restrict__ out) {
    int b = blockIdx.x;
    int g = threadIdx.x;
    out[65536 + ((size_t)b * T + 0) * H + g] = 0.0f;
    out[65536 + (((size_t)B + b) * T + (T - 1)) * H + g] = 0.0f;
}

// ---------------- kernel 4: final linear -> ic_mean, ic_std ----------------
__global__ void final_linear(const float* __restrict__ Wl,
                             const float* __restrict__ bl,
                             float* __restrict__ out) {
    __shared__ float hsm[2 * H];
    int b = blockIdx.x;
    int j = threadIdx.x;
    hsm[j] = g_hfinal[(size_t)b * H + j];
    hsm[H + j] = g_hfinal[((size_t)B + b) * H + j];
    __syncthreads();

    float acc = bl[j];
    const float4* w = (const float4*)&Wl[(size_t)j * (2 * H)];
    #pragma unroll 8
    for (int k4 = 0; k4 < (2 * H) / 4; k4++) {
        float4 wv = w[k4];
        float4 hv = *(const float4*)&hsm[k4 * 4];
        acc += wv.x * hv.x + wv.y * hv.y + wv.z * hv.z + wv.w * hv.w;
    }
    if (j < 64) out[(size_t)b * 64 + j] = acc;
    else out[32768 + (size_t)b * 64 + (j - 64)] = expf(acc);
}

// ---------------- launch ----------------
extern "C" void kernel_launch(void* const* d_in, const int* in_sizes, int n_in,
                              void* d_out, int out_size) {
    const float* data   = (const float*)d_in[0];
    const float* ic_h0  = (const float*)d_in[1];
    const float* ci_h0  = (const float*)d_in[2];
    const float* ic_Wih = (const float*)d_in[3];
    const float* ic_bih = (const float*)d_in[4];
    const float* ic_Whh = (const float*)d_in[5];
    const float* ic_bhh = (const float*)d_in[6];
    const float* ci_Wih = (const float*)d_in[7];
    const float* ci_bih = (const float*)d_in[8];
    const float* ci_Whh = (const float*)d_in[9];
    const float* ci_bhh = (const float*)d_in[10];
    const float* Wl     = (const float*)d_in[11];
    const float* bl     = (const float*)d_in[12];
    float* out = (float*)d_out;

    cudaFuncSetAttribute(scan_kernel, cudaFuncAttributeMaxDynamicSharedMemorySize, SMEM_SCAN);
    cudaFuncSetAttribute(proj_hmma, cudaFuncAttributeMaxDynamicSharedMemorySize, SMEM_PROJ);

    repack_whh<<<(NDIR * G * H + 255) / 256, 256>>>(ic_Whh, ci_Whh);
    conv_data<<<(int)((size_t)B * T * D / 4 / 256), 256>>>(data);
    conv_w<<<NTOT, 256>>>(ic_Wih, ic_bih, ci_Wih, ci_bih, ic_bhh, ci_bhh);

    dim3 pgrid(NTOT / 128, B * T / 128);   // 12 x 2048
    proj_hmma<<<pgrid, 256, SMEM_PROJ>>>();

    scan_kernel<<<NDIR * (B / RT), 256, SMEM_SCAN>>>(ic_h0, ci_h0, out);

    zero_pads<<<B, H>>>(out);
    final_linear<<<B, H>>>(Wl, bl, out);
}

// round 16
// speedup vs baseline: 2.0732x; 2.0311x over previous
#include <cuda_runtime.h>
#include <cuda_bf16.h>
#include <cuda_fp16.h>
#include <stdint.h>
#include <math.h>

#define B 512
#define T 512
#define D 256
#define H 128        // IC_ENC == CI_ENC == 128
#define G 384        // 3*H
#define NDIR 4       // 0=ic_fwd, 1=ic_bwd, 2=ci_fwd, 3=ci_bwd
#define CLIPV 5.0f
#define KP 256       // K' = D (hi-only fp16 GEMM)
#define NTOT (NDIR * G)   // 1536

// ---------------- device scratch (no runtime allocation allowed) ----------------
__device__ float g_xall[(size_t)B * T * NTOT];              // 1.61 GB
__device__ float g_hfinal[2 * B * H];
__device__ __half g_abf[(size_t)B * T * KP];                // A fp16 hi, 134 MB
__device__ __half g_bbf[(size_t)NTOT * KP];                 // B fp16 hi
__device__ float g_bias[NTOT];                              // bih + bhh (folded)

// ---------------- helpers ----------------
__device__ __forceinline__ float sigm(float x) {
    return __fdividef(1.0f, 1.0f + __expf(-x));
}
__device__ __forceinline__ float fast_tanh(float x) {
    float e = __expf(2.0f * x);
    return 1.0f - __fdividef(2.0f, e + 1.0f);
}
__device__ __forceinline__ uint32_t smem_u32(const void* p) {
    uint32_t a;
    asm("{ .reg .u64 t; cvta.to.shared.u64 t, %1; cvt.u32.u64 %0, t; }" : "=r"(a) : "l"(p));
    return a;
}
__device__ __forceinline__ void cpasync16(uint32_t dst, const void* src) {
    asm volatile("cp.async.cg.shared.global [%0], [%1], 16;"
                 :: "r"(dst), "l"(__cvta_generic_to_global(src)) : "memory");
}
__device__ __forceinline__ void cpcommit() {
    asm volatile("cp.async.commit_group;" ::: "memory");
}
__device__ __forceinline__ void cpwait0() {
    asm volatile("cp.async.wait_group 0;" ::: "memory");
}
__device__ __forceinline__ void cpwait1() {
    asm volatile("cp.async.wait_group 1;" ::: "memory");
}
__device__ __forceinline__ void ldsm_x4(uint32_t* r, uint32_t addr) {
    asm volatile("ldmatrix.sync.aligned.m8n8.x4.shared.b16 {%0,%1,%2,%3}, [%4];"
                 : "=r"(r[0]), "=r"(r[1]), "=r"(r[2]), "=r"(r[3]) : "r"(addr));
}
__device__ __forceinline__ void mma16816(float* d, const uint32_t* a, const uint32_t* b) {
    asm volatile(
        "mma.sync.aligned.m16n8k16.row.col.f32.f16.f16.f32 "
        "{%0,%1,%2,%3}, {%4,%5,%6,%7}, {%8,%9}, {%0,%1,%2,%3};"
        : "+f"(d[0]), "+f"(d[1]), "+f"(d[2]), "+f"(d[3])
        : "r"(a[0]), "r"(a[1]), "r"(a[2]), "r"(a[3]), "r"(b[0]), "r"(b[1]));
}

// ---------------- kernel 0b: data -> fp16 (hi only) -----------------------------
__global__ __launch_bounds__(256) void conv_data(const float* __restrict__ data) {
    size_t i4 = (size_t)blockIdx.x * 256 + threadIdx.x;   // float4 index
    float4 v = ((const float4*)data)[i4];
    ushort4 hv;
    hv.x = __half_as_ushort(__float2half_rn(v.x));
    hv.y = __half_as_ushort(__float2half_rn(v.y));
    hv.z = __half_as_ushort(__float2half_rn(v.z));
    hv.w = __half_as_ushort(__float2half_rn(v.w));
    *(ushort4*)&g_abf[i4 * 4] = hv;
}

// ---------------- kernel 0c: weights -> fp16 hi + folded bias --------------------
__global__ __launch_bounds__(256) void conv_w(
    const float* __restrict__ icWih, const float* __restrict__ icBih,
    const float* __restrict__ ciWih, const float* __restrict__ ciBih,
    const float* __restrict__ icBhh, const float* __restrict__ ciBhh) {
    int idx = blockIdx.x * 256 + threadIdx.x;   // n*256 + k
    int n = idx >> 8;
    int k = idx & 255;
    int dir = n / G;
    int g = n - dir * G;
    const float* Wsel = (dir < 2) ? (icWih + (size_t)dir * G * D)
                                  : (ciWih + (size_t)(dir - 2) * G * D);
    const float* Bsel = (dir < 2) ? (icBih + dir * G) : (ciBih + (dir - 2) * G);
    const float* Bhh  = (dir < 2) ? (icBhh + dir * G) : (ciBhh + (dir - 2) * G);
    float x = Wsel[(size_t)g * D + k];
    g_bbf[(size_t)n * KP + k] = __float2half_rn(x);
    if (k == 0) g_bias[n] = Bsel[g] + Bhh[g];   // fold recurrent bias
}

// ---------------- kernel 1: projection GEMM via mma.sync fp16 (HMMA) ------------
#define BK 64
#define NCH (KP / BK)      // 4
#define LDS_STRIDE 144     // bytes per smem row (64 fp16 + 8 pad)
#define STG_B (128 * LDS_STRIDE)            // 18432 B per stage per matrix
#define SMEM_PROJ (3 * STG_B * 2 + 512)     // 111104 B

__global__ __launch_bounds__(256, 2) void proj_hmma() {
    extern __shared__ char psm[];
    uint32_t sA = smem_u32(psm);
    uint32_t sB = sA + 3 * STG_B;
    float* bias_sm = (float*)(psm + 6 * STG_B);

    int tid = threadIdx.x;
    int wid = tid >> 5;
    int lid = tid & 31;
    int wm = wid >> 1;            // 0..3
    int wn = wid & 1;             // 0..1

    int n0 = blockIdx.x * 128;            // 12 N-tiles (fastest -> A reuse in L2)
    size_t m0 = (size_t)blockIdx.y * 128; // 2048 M-tiles

    if (tid < 128) bias_sm[tid] = g_bias[n0 + tid];

    const __half* Ag = g_abf + m0 * KP;
    const __half* Bg = g_bbf + (size_t)n0 * KP;

    int aRow = wm * 32 + (lid & 15);
    int aCol = (lid >> 4) * 16;
    int bRow4 = wn * 64 + ((lid >> 4) * 8) + (lid & 7);
    int bCol4 = ((lid >> 3) & 1) * 16;

    float acc[2][8][4];
    #pragma unroll
    for (int mi = 0; mi < 2; mi++)
        #pragma unroll
        for (int nj = 0; nj < 8; nj++)
            #pragma unroll
            for (int q = 0; q < 4; q++) acc[mi][nj][q] = 0.0f;

    #define LOAD_CHUNK(stg, c) do {                                            \
        uint32_t dA = sA + (stg) * STG_B;                                      \
        uint32_t dB = sB + (stg) * STG_B;                                      \
        int ko = (c) * BK;                                                     \
        _Pragma("unroll")                                                      \
        for (int l = 0; l < 4; l++) {                                          \
            int idx = tid + 256 * l;                                           \
            int row = idx >> 3;                                                \
            int c16 = idx & 7;                                                 \
            cpasync16(dA + row * LDS_STRIDE + c16 * 16,                        \
                      Ag + (size_t)row * KP + ko + c16 * 8);                   \
            cpasync16(dB + row * LDS_STRIDE + c16 * 16,                        \
                      Bg + (size_t)row * KP + ko + c16 * 8);                   \
        }                                                                      \
        cpcommit();                                                            \
    } while (0)

    LOAD_CHUNK(0, 0);
    LOAD_CHUNK(1, 1);

    for (int i = 0; i < NCH; i++) {
        if (i == NCH - 1) cpwait0(); else cpwait1();
        __syncthreads();

        if (i + 2 < NCH) LOAD_CHUNK((i + 2) % 3, i + 2);

        uint32_t aBase = sA + (i % 3) * STG_B;
        uint32_t bBase = sB + (i % 3) * STG_B;
        #pragma unroll
        for (int ks = 0; ks < 4; ks++) {
            uint32_t afr[2][4];
            #pragma unroll
            for (int mi = 0; mi < 2; mi++)
                ldsm_x4(afr[mi], aBase + (aRow + mi * 16) * LDS_STRIDE + ks * 32 + aCol);
            uint32_t bfr[8][2];
            #pragma unroll
            for (int nj2 = 0; nj2 < 4; nj2++) {
                uint32_t q[4];
                ldsm_x4(q, bBase + (bRow4 + nj2 * 16) * LDS_STRIDE + ks * 32 + bCol4);
                bfr[nj2 * 2][0] = q[0]; bfr[nj2 * 2][1] = q[1];
                bfr[nj2 * 2 + 1][0] = q[2]; bfr[nj2 * 2 + 1][1] = q[3];
            }
            #pragma unroll
            for (int mi = 0; mi < 2; mi++)
                #pragma unroll
                for (int nj = 0; nj < 8; nj++)
                    mma16816(acc[mi][nj], afr[mi], bfr[nj]);
        }
    }

    int qr = lid >> 2;
    int qc = (lid & 3) * 2;
    #pragma unroll
    for (int mi = 0; mi < 2; mi++) {
        #pragma unroll
        for (int nj = 0; nj < 8; nj++) {
            int lc = wn * 64 + nj * 8 + qc;
            size_t row = m0 + wm * 32 + mi * 16 + qr;
            float2 v0, v1;
            v0.x = acc[mi][nj][0] + bias_sm[lc];
            v0.y = acc[mi][nj][1] + bias_sm[lc + 1];
            v1.x = acc[mi][nj][2] + bias_sm[lc];
            v1.y = acc[mi][nj][3] + bias_sm[lc + 1];
            *(float2*)&g_xall[row * NTOT + n0 + lc] = v0;
            *(float2*)&g_xall[(row + 8) * NTOT + n0 + lc] = v1;
        }
    }
}

// ---------------- kernel 2: recurrent scan on TENSOR CORES ---------------------
// 256 threads = 8 warps. Warp w owns gate columns [16w, 16w+16).
// GEMM1: z at n=16w, r at n=128+16w; GEMM2: n=256+16w -> z, r, h stay in
// C-fragment registers across the whole step.
// W_hh fp16 hi+lo in SMEM (stride 136 fp16 = 272 B, conflict-free ldmatrix);
// h and rh as fp16 hi/lo 16x136 tiles. Products: Ah*Whi + Al*Whi + Ah*Wlo.
#define RT 16
#define WST 272            // bytes per 136-fp16 smem row
#define WHI_OFF 0
#define WLO_OFF 104448
#define HHI_OFF 208896
#define HLO_OFF 213248
#define RHHI_OFF 217600
#define RHLO_OFF 221952
#define SMEM_SCAN 226304

__global__ __launch_bounds__(256) void scan_kernel(
    const float* __restrict__ icWhh, const float* __restrict__ ciWhh,
    const float* __restrict__ icH0, const float* __restrict__ ciH0,
    float* __restrict__ out) {

    extern __shared__ char ssm[];
    uint32_t sWhi = smem_u32(ssm) + WHI_OFF;
    uint32_t sWlo = smem_u32(ssm) + WLO_OFF;
    uint32_t sHhi = smem_u32(ssm) + HHI_OFF;
    uint32_t sHlo = smem_u32(ssm) + HLO_OFF;
    uint32_t sRhi = smem_u32(ssm) + RHHI_OFF;
    uint32_t sRlo = smem_u32(ssm) + RHLO_OFF;

    int tid = threadIdx.x;
    int w = tid >> 5;
    int lane = tid & 31;

    int dir = blockIdx.x >> 5;
    int tile = blockIdx.x & 31;
    int b0 = tile * RT;

    const float* wsrc = (dir < 2) ? (icWhh + (size_t)dir * G * H)
                                  : (ciWhh + (size_t)(dir - 2) * G * H);
    const float* h0 = (dir < 2) ? (icH0 + dir * H) : (ciH0 + (dir - 2) * H);

    // convert Whh [384][128] fp32 -> fp16 hi/lo in SMEM
    for (int i = tid; i < G * H; i += 256) {
        int g = i >> 7, k = i & 127;
        float v = wsrc[(size_t)g * H + k];
        __half hi = __float2half_rn(v);
        __half lo = __float2half_rn(v - __half2float(hi));
        *(__half*)(ssm + WHI_OFF + g * WST + k * 2) = hi;
        *(__half*)(ssm + WLO_OFF + g * WST + k * 2) = lo;
    }

    // thread-owned positions: rows rl[2], col pairs c(j) = 16w + 8j + 2*(lane&3)
    int rl0 = lane >> 2;
    int cb0 = w * 16 + 2 * (lane & 3);        // tile j=0 pair base
    // init h registers + fp16 tiles
    float hreg[2][2][2];
    #pragma unroll
    for (int i = 0; i < 2; i++)
        #pragma unroll
        for (int j = 0; j < 2; j++) {
            int c = cb0 + j * 8;
            float v0 = h0[c], v1 = h0[c + 1];
            hreg[i][j][0] = v0; hreg[i][j][1] = v1;
            int r = rl0 + i * 8;
            __half p0 = __float2half_rn(v0), p1 = __float2half_rn(v1);
            *(__half2*)(ssm + HHI_OFF + r * WST + c * 2) = __halves2half2(p0, p1);
            *(__half2*)(ssm + HLO_OFF + r * WST + c * 2) =
                __halves2half2(__float2half_rn(v0 - __half2float(p0)),
                               __float2half_rn(v1 - __half2float(p1)));
        }
    __syncthreads();

    // preload W-hi fragments into registers
    int bRow = ((lane >> 4) * 8) + (lane & 7);
    int bCol = ((lane >> 3) & 1) * 16;
    uint32_t WZ[8][2][2], WR[8][2][2], WN[8][2][2];
    #pragma unroll
    for (int ks = 0; ks < 8; ks++) {
        uint32_t q[4];
        ldsm_x4(q, sWhi + (w * 16 + bRow) * WST + ks * 32 + bCol);
        WZ[ks][0][0] = q[0]; WZ[ks][0][1] = q[1]; WZ[ks][1][0] = q[2]; WZ[ks][1][1] = q[3];
        ldsm_x4(q, sWhi + (128 + w * 16 + bRow) * WST + ks * 32 + bCol);
        WR[ks][0][0] = q[0]; WR[ks][0][1] = q[1]; WR[ks][1][0] = q[2]; WR[ks][1][1] = q[3];
        ldsm_x4(q, sWhi + (256 + w * 16 + bRow) * WST + ks * 32 + bCol);
        WN[ks][0][0] = q[0]; WN[ks][0][1] = q[1]; WN[ks][1][0] = q[2]; WN[ks][1][1] = q[3];
    }

    const bool backward = (dir & 1);
    const bool is_ci = (dir >= 2);
    const float* xbase = g_xall + (size_t)b0 * T * NTOT + dir * G;
    const size_t rowstride = (size_t)T * NTOT;

    uint32_t aOff = (lane & 15) * WST + ((lane >> 4) * 16);

    for (int step = 0; step < T; step++) {
        int t = backward ? (T - 1 - step) : step;
        const float* xt = xbase + (size_t)t * NTOT;

        // x loads (float2 pairs) for owned positions
        float2 xz[2][2], xr[2][2], xn[2][2];
        #pragma unroll
        for (int i = 0; i < 2; i++) {
            const float* xrow = xt + (size_t)(rl0 + i * 8) * rowstride;
            #pragma unroll
            for (int j = 0; j < 2; j++) {
                int c = cb0 + j * 8;
                xz[i][j] = *(const float2*)(xrow + c);
                xr[i][j] = *(const float2*)(xrow + c + 128);
                xn[i][j] = *(const float2*)(xrow + c + 256);
            }
        }

        // ---- GEMM1: z and r pre-activations ----
        float zacc[2][4], racc[2][4];
        #pragma unroll
        for (int j = 0; j < 2; j++)
            #pragma unroll
            for (int q = 0; q < 4; q++) { zacc[j][q] = 0.0f; racc[j][q] = 0.0f; }

        #pragma unroll
        for (int ks = 0; ks < 8; ks++) {
            uint32_t Ah[4], Al[4], qz[4], qr[4];
            ldsm_x4(Ah, sHhi + aOff + ks * 32);
            ldsm_x4(Al, sHlo + aOff + ks * 32);
            ldsm_x4(qz, sWlo + (w * 16 + bRow) * WST + ks * 32 + bCol);
            ldsm_x4(qr, sWlo + (128 + w * 16 + bRow) * WST + ks * 32 + bCol);
            mma16816(zacc[0], Ah, WZ[ks][0]);
            mma16816(zacc[1], Ah, WZ[ks][1]);
            mma16816(racc[0], Ah, WR[ks][0]);
            mma16816(racc[1], Ah, WR[ks][1]);
            mma16816(zacc[0], Al, WZ[ks][0]);
            mma16816(zacc[1], Al, WZ[ks][1]);
            mma16816(racc[0], Al, WR[ks][0]);
            mma16816(racc[1], Al, WR[ks][1]);
            mma16816(zacc[0], Ah, qz + 0);
            mma16816(zacc[1], Ah, qz + 2);
            mma16816(racc[0], Ah, qr + 0);
            mma16816(racc[1], Ah, qr + 2);
        }

        // ---- gates: z stays in regs; rh -> fp16 hi/lo tiles ----
        float z[2][2][2];
        #pragma unroll
        for (int i = 0; i < 2; i++)
            #pragma unroll
            for (int j = 0; j < 2; j++) {
                float z0 = sigm(xz[i][j].x + zacc[j][i * 2 + 0]);
                float z1 = sigm(xz[i][j].y + zacc[j][i * 2 + 1]);
                z[i][j][0] = z0; z[i][j][1] = z1;
                float r0 = sigm(xr[i][j].x + racc[j][i * 2 + 0]);
                float r1 = sigm(xr[i][j].y + racc[j][i * 2 + 1]);
                float v0 = r0 * hreg[i][j][0];
                float v1 = r1 * hreg[i][j][1];
                int r = rl0 + i * 8;
                int c = cb0 + j * 8;
                __half p0 = __float2half_rn(v0), p1 = __float2half_rn(v1);
                *(__half2*)(ssm + RHHI_OFF + r * WST + c * 2) = __halves2half2(p0, p1);
                *(__half2*)(ssm + RHLO_OFF + r * WST + c * 2) =
                    __halves2half2(__float2half_rn(v0 - __half2float(p0)),
                                   __float2half_rn(v1 - __half2float(p1)));
            }
        __syncthreads();

        // ---- GEMM2: n pre-activation ----
        float nacc[2][4];
        #pragma unroll
        for (int j = 0; j < 2; j++)
            #pragma unroll
            for (int q = 0; q < 4; q++) nacc[j][q] = 0.0f;

        #pragma unroll
        for (int ks = 0; ks < 8; ks++) {
            uint32_t Ah[4], Al[4], qn[4];
            ldsm_x4(Ah, sRhi + aOff + ks * 32);
            ldsm_x4(Al, sRlo + aOff + ks * 32);
            ldsm_x4(qn, sWlo + (256 + w * 16 + bRow) * WST + ks * 32 + bCol);
            mma16816(nacc[0], Ah, WN[ks][0]);
            mma16816(nacc[1], Ah, WN[ks][1]);
            mma16816(nacc[0], Al, WN[ks][0]);
            mma16816(nacc[1], Al, WN[ks][1]);
            mma16816(nacc[0], Ah, qn + 0);
            mma16816(nacc[1], Ah, qn + 2);
        }

        // ---- update h ----
        int slot = is_ci ? (dir == 2 ? t + 1 : t - 1) : 0;
        #pragma unroll
        for (int i = 0; i < 2; i++)
            #pragma unroll
            for (int j = 0; j < 2; j++) {
                float n0 = fast_tanh(xn[i][j].x + nacc[j][i * 2 + 0]);
                float n1 = fast_tanh(xn[i][j].y + nacc[j][i * 2 + 1]);
                float h0n = z[i][j][0] * hreg[i][j][0] + (1.0f - z[i][j][0]) * n0;
                float h1n = z[i][j][1] * hreg[i][j][1] + (1.0f - z[i][j][1]) * n1;
                h0n = fminf(CLIPV, fmaxf(-CLIPV, h0n));
                h1n = fminf(CLIPV, fmaxf(-CLIPV, h1n));
                hreg[i][j][0] = h0n; hreg[i][j][1] = h1n;
                int r = rl0 + i * 8;
                int c = cb0 + j * 8;
                __half p0 = __float2half_rn(h0n), p1 = __float2half_rn(h1n);
                *(__half2*)(ssm + HHI_OFF + r * WST + c * 2) = __halves2half2(p0, p1);
                *(__half2*)(ssm + HLO_OFF + r * WST + c * 2) =
                    __halves2half2(__float2half_rn(h0n - __half2float(p0)),
                                   __float2half_rn(h1n - __half2float(p1)));
                if (is_ci && slot >= 0 && slot < T) {
                    float2 o2; o2.x = h0n; o2.y = h1n;
                    size_t o = 65536 + (((size_t)(dir - 2) * B + (b0 + r)) * T + slot) * H + c;
                    *(float2*)&out[o] = o2;
                }
            }
        __syncthreads();
    }

    if (dir < 2) {
        #pragma unroll
        for (int i = 0; i < 2; i++)
            #pragma unroll
            for (int j = 0; j < 2; j++) {
                int r = rl0 + i * 8;
                int c = cb0 + j * 8;
                float2 o2; o2.x = hreg[i][j][0]; o2.y = hreg[i][j][1];
                *(float2*)&g_hfinal[((size_t)dir * B + b0 + r) * H + c] = o2;
            }
    }
}

// ---------------- kernel 3: zero the lag-pad slots of ci ----------------
__global__ void zero_pads(float* __restrict__ out) {
    int b = blockIdx.x;
    int g = threadIdx.x;
    out[65536 + ((size_t)b * T + 0) * H + g] = 0.0f;
    out[65536 + (((size_t)B + b) * T + (T - 1)) * H + g] = 0.0f;
}

// ---------------- kernel 4: final linear -> ic_mean, ic_std ----------------
__global__ void final_linear(const float* __restrict__ Wl,
                             const float* __restrict__ bl,
                             float* __restrict__ out) {
    __shared__ float hsm[2 * H];
    int b = blockIdx.x;
    int j = threadIdx.x;
    hsm[j] = g_hfinal[(size_t)b * H + j];
    hsm[H + j] = g_hfinal[((size_t)B + b) * H + j];
    __syncthreads();

    float acc = bl[j];
    const float4* w = (const float4*)&Wl[(size_t)j * (2 * H)];
    #pragma unroll 8
    for (int k4 = 0; k4 < (2 * H) / 4; k4++) {
        float4 wv = w[k4];
        float4 hv = *(const float4*)&hsm[k4 * 4];
        acc += wv.x * hv.x + wv.y * hv.y + wv.z * hv.z + wv.w * hv.w;
    }
    if (j < 64) out[(size_t)b * 64 + j] = acc;
    else out[32768 + (size_t)b * 64 + (j - 64)] = expf(acc);
}

// ---------------- launch ----------------
extern "C" void kernel_launch(void* const* d_in, const int* in_sizes, int n_in,
                              void* d_out, int out_size) {
    const float* data   = (const float*)d_in[0];
    const float* ic_h0  = (const float*)d_in[1];
    const float* ci_h0  = (const float*)d_in[2];
    const float* ic_Wih = (const float*)d_in[3];
    const float* ic_bih = (const float*)d_in[4];
    const float* ic_Whh = (const float*)d_in[5];
    const float* ic_bhh = (const float*)d_in[6];
    const float* ci_Wih = (const float*)d_in[7];
    const float* ci_bih = (const float*)d_in[8];
    const float* ci_Whh = (const float*)d_in[9];
    const float* ci_bhh = (const float*)d_in[10];
    const float* Wl     = (const float*)d_in[11];
    const float* bl     = (const float*)d_in[12];
    float* out = (float*)d_out;

    cudaFuncSetAttribute(scan_kernel, cudaFuncAttributeMaxDynamicSharedMemorySize, SMEM_SCAN);
    cudaFuncSetAttribute(proj_hmma, cudaFuncAttributeMaxDynamicSharedMemorySize, SMEM_PROJ);

    conv_data<<<(int)((size_t)B * T * D / 4 / 256), 256>>>(data);
    conv_w<<<NTOT, 256>>>(ic_Wih, ic_bih, ci_Wih, ci_bih, ic_bhh, ci_bhh);

    dim3 pgrid(NTOT / 128, B * T / 128);   // 12 x 2048
    proj_hmma<<<pgrid, 256, SMEM_PROJ>>>();

    scan_kernel<<<NDIR * (B / RT), 256, SMEM_SCAN>>>(ic_Whh, ci_Whh, ic_h0, ci_h0, out);

    zero_pads<<<B, H>>>(out);
    final_linear<<<B, H>>>(Wl, bl, out);
}

// round 17
// speedup vs baseline: 2.3583x; 1.1375x over previous
#include <cuda_runtime.h>
#include <cuda_bf16.h>
#include <cuda_fp16.h>
#include <stdint.h>
#include <math.h>

#define B 512
#define T 512
#define D 256
#define H 128        // IC_ENC == CI_ENC == 128
#define G 384        // 3*H
#define NDIR 4       // 0=ic_fwd, 1=ic_bwd, 2=ci_fwd, 3=ci_bwd
#define CLIPV 5.0f
#define KP 256       // K' = D (hi-only fp16 GEMM)
#define NTOT (NDIR * G)   // 1536

// ---------------- device scratch (no runtime allocation allowed) ----------------
__device__ __half g_xall[(size_t)B * T * NTOT];             // fp16, 0.8 GB
__device__ float g_hfinal[2 * B * H];
__device__ __half g_abf[(size_t)B * T * KP];                // A fp16 hi, 134 MB
__device__ __half g_bbf[(size_t)NTOT * KP];                 // B fp16 hi
__device__ float g_bias[NTOT];                              // bih + bhh (folded)

// ---------------- helpers ----------------
__device__ __forceinline__ float sigm(float x) {
    return __fdividef(1.0f, 1.0f + __expf(-x));
}
__device__ __forceinline__ float fast_tanh(float x) {
    float e = __expf(2.0f * x);
    return 1.0f - __fdividef(2.0f, e + 1.0f);
}
__device__ __forceinline__ uint32_t smem_u32(const void* p) {
    uint32_t a;
    asm("{ .reg .u64 t; cvta.to.shared.u64 t, %1; cvt.u32.u64 %0, t; }" : "=r"(a) : "l"(p));
    return a;
}
__device__ __forceinline__ void cpasync16(uint32_t dst, const void* src) {
    asm volatile("cp.async.cg.shared.global [%0], [%1], 16;"
                 :: "r"(dst), "l"(__cvta_generic_to_global(src)) : "memory");
}
__device__ __forceinline__ void cpcommit() {
    asm volatile("cp.async.commit_group;" ::: "memory");
}
__device__ __forceinline__ void cpwait0() {
    asm volatile("cp.async.wait_group 0;" ::: "memory");
}
__device__ __forceinline__ void cpwait1() {
    asm volatile("cp.async.wait_group 1;" ::: "memory");
}
__device__ __forceinline__ void ldsm_x4(uint32_t* r, uint32_t addr) {
    asm volatile("ldmatrix.sync.aligned.m8n8.x4.shared.b16 {%0,%1,%2,%3}, [%4];"
                 : "=r"(r[0]), "=r"(r[1]), "=r"(r[2]), "=r"(r[3]) : "r"(addr));
}
__device__ __forceinline__ void mma16816(float* d, const uint32_t* a, const uint32_t* b) {
    asm volatile(
        "mma.sync.aligned.m16n8k16.row.col.f32.f16.f16.f32 "
        "{%0,%1,%2,%3}, {%4,%5,%6,%7}, {%8,%9}, {%0,%1,%2,%3};"
        : "+f"(d[0]), "+f"(d[1]), "+f"(d[2]), "+f"(d[3])
        : "r"(a[0]), "r"(a[1]), "r"(a[2]), "r"(a[3]), "r"(b[0]), "r"(b[1]));
}

// ---------------- kernel 0b: data -> fp16 (hi only) -----------------------------
__global__ __launch_bounds__(256) void conv_data(const float* __restrict__ data) {
    size_t i4 = (size_t)blockIdx.x * 256 + threadIdx.x;   // float4 index
    float4 v = ((const float4*)data)[i4];
    ushort4 hv;
    hv.x = __half_as_ushort(__float2half_rn(v.x));
    hv.y = __half_as_ushort(__float2half_rn(v.y));
    hv.z = __half_as_ushort(__float2half_rn(v.z));
    hv.w = __half_as_ushort(__float2half_rn(v.w));
    *(ushort4*)&g_abf[i4 * 4] = hv;
}

// ---------------- kernel 0c: weights -> fp16 hi + folded bias --------------------
__global__ __launch_bounds__(256) void conv_w(
    const float* __restrict__ icWih, const float* __restrict__ icBih,
    const float* __restrict__ ciWih, const float* __restrict__ ciBih,
    const float* __restrict__ icBhh, const float* __restrict__ ciBhh) {
    int idx = blockIdx.x * 256 + threadIdx.x;   // n*256 + k
    int n = idx >> 8;
    int k = idx & 255;
    int dir = n / G;
    int g = n - dir * G;
    const float* Wsel = (dir < 2) ? (icWih + (size_t)dir * G * D)
                                  : (ciWih + (size_t)(dir - 2) * G * D);
    const float* Bsel = (dir < 2) ? (icBih + dir * G) : (ciBih + (dir - 2) * G);
    const float* Bhh  = (dir < 2) ? (icBhh + dir * G) : (ciBhh + (dir - 2) * G);
    float x = Wsel[(size_t)g * D + k];
    g_bbf[(size_t)n * KP + k] = __float2half_rn(x);
    if (k == 0) g_bias[n] = Bsel[g] + Bhh[g];   // fold recurrent bias
}

// ---------------- kernel 1: projection GEMM via mma.sync fp16 (HMMA) ------------
#define BK 64
#define NCH (KP / BK)      // 4
#define LDS_STRIDE 144     // bytes per smem row (64 fp16 + 8 pad)
#define STG_B (128 * LDS_STRIDE)            // 18432 B per stage per matrix
#define SMEM_PROJ (3 * STG_B * 2 + 512)     // 111104 B

__global__ __launch_bounds__(256, 2) void proj_hmma() {
    extern __shared__ char psm[];
    uint32_t sA = smem_u32(psm);
    uint32_t sB = sA + 3 * STG_B;
    float* bias_sm = (float*)(psm + 6 * STG_B);

    int tid = threadIdx.x;
    int wid = tid >> 5;
    int lid = tid & 31;
    int wm = wid >> 1;            // 0..3
    int wn = wid & 1;             // 0..1

    int n0 = blockIdx.x * 128;            // 12 N-tiles (fastest -> A reuse in L2)
    size_t m0 = (size_t)blockIdx.y * 128; // 2048 M-tiles

    if (tid < 128) bias_sm[tid] = g_bias[n0 + tid];

    const __half* Ag = g_abf + m0 * KP;
    const __half* Bg = g_bbf + (size_t)n0 * KP;

    int aRow = wm * 32 + (lid & 15);
    int aCol = (lid >> 4) * 16;
    int bRow4 = wn * 64 + ((lid >> 4) * 8) + (lid & 7);
    int bCol4 = ((lid >> 3) & 1) * 16;

    float acc[2][8][4];
    #pragma unroll
    for (int mi = 0; mi < 2; mi++)
        #pragma unroll
        for (int nj = 0; nj < 8; nj++)
            #pragma unroll
            for (int q = 0; q < 4; q++) acc[mi][nj][q] = 0.0f;

    #define LOAD_CHUNK(stg, c) do {                                            \
        uint32_t dA = sA + (stg) * STG_B;                                      \
        uint32_t dB = sB + (stg) * STG_B;                                      \
        int ko = (c) * BK;                                                     \
        _Pragma("unroll")                                                      \
        for (int l = 0; l < 4; l++) {                                          \
            int idx = tid + 256 * l;                                           \
            int row = idx >> 3;                                                \
            int c16 = idx & 7;                                                 \
            cpasync16(dA + row * LDS_STRIDE + c16 * 16,                        \
                      Ag + (size_t)row * KP + ko + c16 * 8);                   \
            cpasync16(dB + row * LDS_STRIDE + c16 * 16,                        \
                      Bg + (size_t)row * KP + ko + c16 * 8);                   \
        }                                                                      \
        cpcommit();                                                            \
    } while (0)

    LOAD_CHUNK(0, 0);
    LOAD_CHUNK(1, 1);

    for (int i = 0; i < NCH; i++) {
        if (i == NCH - 1) cpwait0(); else cpwait1();
        __syncthreads();

        if (i + 2 < NCH) LOAD_CHUNK((i + 2) % 3, i + 2);

        uint32_t aBase = sA + (i % 3) * STG_B;
        uint32_t bBase = sB + (i % 3) * STG_B;
        #pragma unroll
        for (int ks = 0; ks < 4; ks++) {
            uint32_t afr[2][4];
            #pragma unroll
            for (int mi = 0; mi < 2; mi++)
                ldsm_x4(afr[mi], aBase + (aRow + mi * 16) * LDS_STRIDE + ks * 32 + aCol);
            uint32_t bfr[8][2];
            #pragma unroll
            for (int nj2 = 0; nj2 < 4; nj2++) {
                uint32_t q[4];
                ldsm_x4(q, bBase + (bRow4 + nj2 * 16) * LDS_STRIDE + ks * 32 + bCol4);
                bfr[nj2 * 2][0] = q[0]; bfr[nj2 * 2][1] = q[1];
                bfr[nj2 * 2 + 1][0] = q[2]; bfr[nj2 * 2 + 1][1] = q[3];
            }
            #pragma unroll
            for (int mi = 0; mi < 2; mi++)
                #pragma unroll
                for (int nj = 0; nj < 8; nj++)
                    mma16816(acc[mi][nj], afr[mi], bfr[nj]);
        }
    }

    int qr = lid >> 2;
    int qc = (lid & 3) * 2;
    #pragma unroll
    for (int mi = 0; mi < 2; mi++) {
        #pragma unroll
        for (int nj = 0; nj < 8; nj++) {
            int lc = wn * 64 + nj * 8 + qc;
            size_t row = m0 + wm * 32 + mi * 16 + qr;
            __half2 o0 = __halves2half2(
                __float2half_rn(acc[mi][nj][0] + bias_sm[lc]),
                __float2half_rn(acc[mi][nj][1] + bias_sm[lc + 1]));
            __half2 o1 = __halves2half2(
                __float2half_rn(acc[mi][nj][2] + bias_sm[lc]),
                __float2half_rn(acc[mi][nj][3] + bias_sm[lc + 1]));
            *(__half2*)&g_xall[row * NTOT + n0 + lc] = o0;
            *(__half2*)&g_xall[(row + 8) * NTOT + n0 + lc] = o1;
        }
    }
}

// ---------------- kernel 2: recurrent scan on TENSOR CORES ---------------------
// 256 threads = 8 warps. Warp w owns gate columns [16w, 16w+16).
// W_hh fp16 hi only (in registers after preload); h and rh as fp16 hi/lo
// tiles -> products (Ah + Al) * Whi. z, r, h stay in C-fragment registers.
#define RT 16
#define WST 272            // bytes per 136-fp16 smem row
#define WHI_OFF 0
#define HHI_OFF 104448
#define HLO_OFF 108800
#define RHHI_OFF 113152
#define RHLO_OFF 117504
#define SMEM_SCAN 121856

__global__ __launch_bounds__(256) void scan_kernel(
    const float* __restrict__ icWhh, const float* __restrict__ ciWhh,
    const float* __restrict__ icH0, const float* __restrict__ ciH0,
    float* __restrict__ out) {

    extern __shared__ char ssm[];
    uint32_t sWhi = smem_u32(ssm) + WHI_OFF;
    uint32_t sHhi = smem_u32(ssm) + HHI_OFF;
    uint32_t sHlo = smem_u32(ssm) + HLO_OFF;
    uint32_t sRhi = smem_u32(ssm) + RHHI_OFF;
    uint32_t sRlo = smem_u32(ssm) + RHLO_OFF;

    int tid = threadIdx.x;
    int w = tid >> 5;
    int lane = tid & 31;

    int dir = blockIdx.x >> 5;
    int tile = blockIdx.x & 31;
    int b0 = tile * RT;

    const float* wsrc = (dir < 2) ? (icWhh + (size_t)dir * G * H)
                                  : (ciWhh + (size_t)(dir - 2) * G * H);
    const float* h0 = (dir < 2) ? (icH0 + dir * H) : (ciH0 + (dir - 2) * H);

    // convert Whh [384][128] fp32 -> fp16 hi in SMEM
    for (int i = tid; i < G * H; i += 256) {
        int g = i >> 7, k = i & 127;
        *(__half*)(ssm + WHI_OFF + g * WST + k * 2) =
            __float2half_rn(wsrc[(size_t)g * H + k]);
    }

    // thread-owned positions: rows rl[2], col pairs c(j) = 16w + 8j + 2*(lane&3)
    int rl0 = lane >> 2;
    int cb0 = w * 16 + 2 * (lane & 3);
    float hreg[2][2][2];
    #pragma unroll
    for (int i = 0; i < 2; i++)
        #pragma unroll
        for (int j = 0; j < 2; j++) {
            int c = cb0 + j * 8;
            float v0 = h0[c], v1 = h0[c + 1];
            hreg[i][j][0] = v0; hreg[i][j][1] = v1;
            int r = rl0 + i * 8;
            __half p0 = __float2half_rn(v0), p1 = __float2half_rn(v1);
            *(__half2*)(ssm + HHI_OFF + r * WST + c * 2) = __halves2half2(p0, p1);
            *(__half2*)(ssm + HLO_OFF + r * WST + c * 2) =
                __halves2half2(__float2half_rn(v0 - __half2float(p0)),
                               __float2half_rn(v1 - __half2float(p1)));
        }
    __syncthreads();

    // preload W-hi fragments into registers
    int bRow = ((lane >> 4) * 8) + (lane & 7);
    int bCol = ((lane >> 3) & 1) * 16;
    uint32_t WZ[8][2][2], WR[8][2][2], WN[8][2][2];
    #pragma unroll
    for (int ks = 0; ks < 8; ks++) {
        uint32_t q[4];
        ldsm_x4(q, sWhi + (w * 16 + bRow) * WST + ks * 32 + bCol);
        WZ[ks][0][0] = q[0]; WZ[ks][0][1] = q[1]; WZ[ks][1][0] = q[2]; WZ[ks][1][1] = q[3];
        ldsm_x4(q, sWhi + (128 + w * 16 + bRow) * WST + ks * 32 + bCol);
        WR[ks][0][0] = q[0]; WR[ks][0][1] = q[1]; WR[ks][1][0] = q[2]; WR[ks][1][1] = q[3];
        ldsm_x4(q, sWhi + (256 + w * 16 + bRow) * WST + ks * 32 + bCol);
        WN[ks][0][0] = q[0]; WN[ks][0][1] = q[1]; WN[ks][1][0] = q[2]; WN[ks][1][1] = q[3];
    }

    const bool backward = (dir & 1);
    const bool is_ci = (dir >= 2);
    const __half* xbase = g_xall + (size_t)b0 * T * NTOT + dir * G;
    const size_t rowstride = (size_t)T * NTOT;

    uint32_t aOff = (lane & 15) * WST + ((lane >> 4) * 16);

    for (int step = 0; step < T; step++) {
        int t = backward ? (T - 1 - step) : step;
        const __half* xt = xbase + (size_t)t * NTOT;

        // x loads (half2 pairs) for owned positions
        float2 xz[2][2], xr[2][2], xn[2][2];
        #pragma unroll
        for (int i = 0; i < 2; i++) {
            const __half* xrow = xt + (size_t)(rl0 + i * 8) * rowstride;
            #pragma unroll
            for (int j = 0; j < 2; j++) {
                int c = cb0 + j * 8;
                xz[i][j] = __half22float2(*(const __half2*)(xrow + c));
                xr[i][j] = __half22float2(*(const __half2*)(xrow + c + 128));
                xn[i][j] = __half22float2(*(const __half2*)(xrow + c + 256));
            }
        }

        // ---- GEMM1: z and r pre-activations (Ah+Al) * Whi ----
        float zacc[2][4], racc[2][4];
        #pragma unroll
        for (int j = 0; j < 2; j++)
            #pragma unroll
            for (int q = 0; q < 4; q++) { zacc[j][q] = 0.0f; racc[j][q] = 0.0f; }

        #pragma unroll
        for (int ks = 0; ks < 8; ks++) {
            uint32_t Ah[4], Al[4];
            ldsm_x4(Ah, sHhi + aOff + ks * 32);
            ldsm_x4(Al, sHlo + aOff + ks * 32);
            mma16816(zacc[0], Ah, WZ[ks][0]);
            mma16816(zacc[1], Ah, WZ[ks][1]);
            mma16816(racc[0], Ah, WR[ks][0]);
            mma16816(racc[1], Ah, WR[ks][1]);
            mma16816(zacc[0], Al, WZ[ks][0]);
            mma16816(zacc[1], Al, WZ[ks][1]);
            mma16816(racc[0], Al, WR[ks][0]);
            mma16816(racc[1], Al, WR[ks][1]);
        }

        // ---- gates: z stays in regs; rh -> fp16 hi/lo tiles ----
        float z[2][2][2];
        #pragma unroll
        for (int i = 0; i < 2; i++)
            #pragma unroll
            for (int j = 0; j < 2; j++) {
                float z0 = sigm(xz[i][j].x + zacc[j][i * 2 + 0]);
                float z1 = sigm(xz[i][j].y + zacc[j][i * 2 + 1]);
                z[i][j][0] = z0; z[i][j][1] = z1;
                float r0 = sigm(xr[i][j].x + racc[j][i * 2 + 0]);
                float r1 = sigm(xr[i][j].y + racc[j][i * 2 + 1]);
                float v0 = r0 * hreg[i][j][0];
                float v1 = r1 * hreg[i][j][1];
                int r = rl0 + i * 8;
                int c = cb0 + j * 8;
                __half p0 = __float2half_rn(v0), p1 = __float2half_rn(v1);
                *(__half2*)(ssm + RHHI_OFF + r * WST + c * 2) = __halves2half2(p0, p1);
                *(__half2*)(ssm + RHLO_OFF + r * WST + c * 2) =
                    __halves2half2(__float2half_rn(v0 - __half2float(p0)),
                                   __float2half_rn(v1 - __half2float(p1)));
            }
        __syncthreads();

        // ---- GEMM2: n pre-activation ----
        float nacc[2][4];
        #pragma unroll
        for (int j = 0; j < 2; j++)
            #pragma unroll
            for (int q = 0; q < 4; q++) nacc[j][q] = 0.0f;

        #pragma unroll
        for (int ks = 0; ks < 8; ks++) {
            uint32_t Ah[4], Al[4];
            ldsm_x4(Ah, sRhi + aOff + ks * 32);
            ldsm_x4(Al, sRlo + aOff + ks * 32);
            mma16816(nacc[0], Ah, WN[ks][0]);
            mma16816(nacc[1], Ah, WN[ks][1]);
            mma16816(nacc[0], Al, WN[ks][0]);
            mma16816(nacc[1], Al, WN[ks][1]);
        }

        // ---- update h ----
        int slot = is_ci ? (dir == 2 ? t + 1 : t - 1) : 0;
        #pragma unroll
        for (int i = 0; i < 2; i++)
            #pragma unroll
            for (int j = 0; j < 2; j++) {
                float n0 = fast_tanh(xn[i][j].x + nacc[j][i * 2 + 0]);
                float n1 = fast_tanh(xn[i][j].y + nacc[j][i * 2 + 1]);
                float h0n = z[i][j][0] * hreg[i][j][0] + (1.0f - z[i][j][0]) * n0;
                float h1n = z[i][j][1] * hreg[i][j][1] + (1.0f - z[i][j][1]) * n1;
                h0n = fminf(CLIPV, fmaxf(-CLIPV, h0n));
                h1n = fminf(CLIPV, fmaxf(-CLIPV, h1n));
                hreg[i][j][0] = h0n; hreg[i][j][1] = h1n;
                int r = rl0 + i * 8;
                int c = cb0 + j * 8;
                __half p0 = __float2half_rn(h0n), p1 = __float2half_rn(h1n);
                *(__half2*)(ssm + HHI_OFF + r * WST + c * 2) = __halves2half2(p0, p1);
                *(__half2*)(ssm + HLO_OFF + r * WST + c * 2) =
                    __halves2half2(__float2half_rn(h0n - __half2float(p0)),
                                   __float2half_rn(h1n - __half2float(p1)));
                if (is_ci && slot >= 0 && slot < T) {
                    float2 o2; o2.x = h0n; o2.y = h1n;
                    size_t o = 65536 + (((size_t)(dir - 2) * B + (b0 + r)) * T + slot) * H + c;
                    *(float2*)&out[o] = o2;
                }
            }
        __syncthreads();
    }

    if (dir < 2) {
        #pragma unroll
        for (int i = 0; i < 2; i++)
            #pragma unroll
            for (int j = 0; j < 2; j++) {
                int r = rl0 + i * 8;
                int c = cb0 + j * 8;
                float2 o2; o2.x = hreg[i][j][0]; o2.y = hreg[i][j][1];
                *(float2*)&g_hfinal[((size_t)dir * B + b0 + r) * H + c] = o2;
            }
    }
}

// ---------------- kernel 3: zero the lag-pad slots of ci ----------------
__global__ void zero_pads(float* __restrict__ out) {
    int b = blockIdx.x;
    int g = threadIdx.x;
    out[65536 + ((size_t)b * T + 0) * H + g] = 0.0f;
    out[65536 + (((size_t)B + b) * T + (T - 1)) * H + g] = 0.0f;
}

// ---------------- kernel 4: final linear -> ic_mean, ic_std ----------------
__global__ void final_linear(const float* __restrict__ Wl,
                             const float* __restrict__ bl,
                             float* __restrict__ out) {
    __shared__ float hsm[2 * H];
    int b = blockIdx.x;
    int j = threadIdx.x;
    hsm[j] = g_hfinal[(size_t)b * H + j];
    hsm[H + j] = g_hfinal[((size_t)B + b) * H + j];
    __syncthreads();

    float acc = bl[j];
    const float4* w = (const float4*)&Wl[(size_t)j * (2 * H)];
    #pragma unroll 8
    for (int k4 = 0; k4 < (2 * H) / 4; k4++) {
        float4 wv = w[k4];
        float4 hv = *(const float4*)&hsm[k4 * 4];
        acc += wv.x * hv.x + wv.y * hv.y + wv.z * hv.z + wv.w * hv.w;
    }
    if (j < 64) out[(size_t)b * 64 + j] = acc;
    else out[32768 + (size_t)b * 64 + (j - 64)] = expf(acc);
}

// ---------------- launch ----------------
extern "C" void kernel_launch(void* const* d_in, const int* in_sizes, int n_in,
                              void* d_out, int out_size) {
    const float* data   = (const float*)d_in[0];
    const float* ic_h0  = (const float*)d_in[1];
    const float* ci_h0  = (const float*)d_in[2];
    const float* ic_Wih = (const float*)d_in[3];
    const float* ic_bih = (const float*)d_in[4];
    const float* ic_Whh = (const float*)d_in[5];
    const float* ic_bhh = (const float*)d_in[6];
    const float* ci_Wih = (const float*)d_in[7];
    const float* ci_bih = (const float*)d_in[8];
    const float* ci_Whh = (const float*)d_in[9];
    const float* ci_bhh = (const float*)d_in[10];
    const float* Wl     = (const float*)d_in[11];
    const float* bl     = (const float*)d_in[12];
    float* out = (float*)d_out;

    cudaFuncSetAttribute(scan_kernel, cudaFuncAttributeMaxDynamicSharedMemorySize, SMEM_SCAN);
    cudaFuncSetAttribute(proj_hmma, cudaFuncAttributeMaxDynamicSharedMemorySize, SMEM_PROJ);

    conv_data<<<(int)((size_t)B * T * D / 4 / 256), 256>>>(data);
    conv_w<<<NTOT, 256>>>(ic_Wih, ic_bih, ci_Wih, ci_bih, ic_bhh, ci_bhh);

    dim3 pgrid(NTOT / 128, B * T / 128);   // 12 x 2048
    proj_hmma<<<pgrid, 256, SMEM_PROJ>>>();

    scan_kernel<<<NDIR * (B / RT), 256, SMEM_SCAN>>>(ic_Whh, ci_Whh, ic_h0, ci_h0, out);

    zero_pads<<<B, H>>>(out);
    final_linear<<<B, H>>>(Wl, bl, out);
}